// round 15
// baseline (speedup 1.0000x reference)
#include <cuda_runtime.h>
#include <cuda_bf16.h>
#include <cstdint>

#define SQ   2048
#define BB   2
#define HID  1024
#define NH   16
#define DH   64
#define RK   64
#define NT   (SQ*BB)
#define BHN  (BB*NH)
#define CTXE ((size_t)SQ*BB*HID)

typedef unsigned long long u64;

// ---------------- device scratch (no allocation allowed) ----------------
__device__ float g_sq[2][BHN*SQ];          // ||q||^2, ||k||^2
__device__ __nv_bfloat16 g_wat_hi[3*RK*HID], g_wat_lo[3*RK*HID]; // wa^T [n][k]
__device__ __nv_bfloat16 g_wbt_hi[3*HID*RK], g_wbt_lo[3*HID*RK]; // wb^T [n][k]
__device__ __nv_bfloat16 g_thi[3*NT*RK], g_tlo[3*NT*RK];         // A-stage out
__device__ __nv_bfloat16 g_qhi[BHN*SQ*DH], g_qlo[BHN*SQ*DH];
__device__ __nv_bfloat16 g_khi[BHN*SQ*DH], g_klo[BHN*SQ*DH];
__device__ __nv_bfloat16 g_vhi[BHN*SQ*DH], g_vlo[BHN*SQ*DH];

__device__ __forceinline__ uint32_t s2u(const void* p){
    uint32_t a;
    asm("{ .reg .u64 t; cvta.to.shared.u64 t, %1; cvt.u32.u64 %0, t; }" : "=r"(a) : "l"(p));
    return a;
}
__device__ __forceinline__ u64 pk2f(float a, float b){
    u64 r; asm("mov.b64 %0,{%1,%2};" : "=l"(r) : "f"(a), "f"(b)); return r;
}
__device__ __forceinline__ void up2f(u64 v, float& a, float& b){
    asm("mov.b64 {%0,%1},%2;" : "=f"(a), "=f"(b) : "l"(v));
}

// ---------------- mma.sync helpers (baseline ISA) ------
__device__ __forceinline__ void ldmx4(uint32_t& r0, uint32_t& r1, uint32_t& r2, uint32_t& r3,
                                      uint32_t addr){
    asm volatile("ldmatrix.sync.aligned.m8n8.x4.shared.b16 {%0,%1,%2,%3}, [%4];"
        : "=r"(r0), "=r"(r1), "=r"(r2), "=r"(r3) : "r"(addr));
}
__device__ __forceinline__ void ldmx4t(uint32_t& r0, uint32_t& r1, uint32_t& r2, uint32_t& r3,
                                       uint32_t addr){
    asm volatile("ldmatrix.sync.aligned.m8n8.x4.trans.shared.b16 {%0,%1,%2,%3}, [%4];"
        : "=r"(r0), "=r"(r1), "=r"(r2), "=r"(r3) : "r"(addr));
}
__device__ __forceinline__ void mma16816(float* d, const uint32_t* a, uint32_t b0, uint32_t b1){
    asm("mma.sync.aligned.m16n8k16.row.col.f32.bf16.bf16.f32 "
        "{%0,%1,%2,%3},{%4,%5,%6,%7},{%8,%9},{%0,%1,%2,%3};"
        : "+f"(d[0]), "+f"(d[1]), "+f"(d[2]), "+f"(d[3])
        : "r"(a[0]), "r"(a[1]), "r"(a[2]), "r"(a[3]), "r"(b0), "r"(b1));
}
// Packed bf16 hi/lo split.
__device__ __forceinline__ void split2(float x, float y, uint32_t& hi, uint32_t& lo){
    uint32_t h;
    asm("cvt.rn.bf16x2.f32 %0, %1, %2;" : "=r"(h) : "f"(y), "f"(x));
    float xh = __uint_as_float(h << 16);
    float yh = __uint_as_float(h & 0xFFFF0000u);
    float xl = x - xh, yl = y - yh;
    uint32_t l;
    asm("cvt.rn.bf16x2.f32 %0, %1, %2;" : "=r"(l) : "f"(yl), "f"(xl));
    hi = h; lo = l;
}
__device__ __forceinline__ void cpa16(uint32_t dst, const void* src){
    asm volatile("cp.async.cg.shared.global [%0], [%1], 16;" :: "r"(dst), "l"(src));
}
#define CP_COMMIT() asm volatile("cp.async.commit_group;")
#define CP_WAIT(n)  asm volatile("cp.async.wait_group %0;" :: "n"(n))
__device__ __forceinline__ void stg_cs4(float* p, float a, float b, float c, float d){
    asm volatile("st.global.cs.v4.f32 [%0], {%1,%2,%3,%4};"
        :: "l"(p), "f"(a), "f"(b), "f"(c), "f"(d) : "memory");
}

// ---------------------------------------------------------------------------
// Kernel 0: transpose+split weights.
// ---------------------------------------------------------------------------
__global__ void __launch_bounds__(256) k_splitw(
    const float* __restrict__ wqa, const float* __restrict__ wka, const float* __restrict__ wva,
    const float* __restrict__ wqb, const float* __restrict__ wkb, const float* __restrict__ wvb)
{
    const int mat = blockIdx.z;
    if (blockIdx.y == 0){
        const float* wa = (mat==0) ? wqa : (mat==1 ? wka : wva);
#pragma unroll
        for (int it = 0; it < 8; it++){
            int o2 = (blockIdx.x*2048 + it*256 + threadIdx.x)*2;
            int n = o2 >> 10, k = o2 & 1023;
            float v0 = wa[(size_t)k*RK + n];
            float v1 = wa[(size_t)(k+1)*RK + n];
            uint32_t h, l; split2(v0, v1, h, l);
            *reinterpret_cast<uint32_t*>(g_wat_hi + (size_t)mat*RK*HID + o2) = h;
            *reinterpret_cast<uint32_t*>(g_wat_lo + (size_t)mat*RK*HID + o2) = l;
        }
    } else {
        const float* wb = (mat==0) ? wqb : (mat==1 ? wkb : wvb);
#pragma unroll
        for (int it = 0; it < 8; it++){
            int o2 = (blockIdx.x*2048 + it*256 + threadIdx.x)*2;
            int n = o2 >> 6, k = o2 & 63;
            float v0 = wb[(size_t)k*HID + n];
            float v1 = wb[(size_t)(k+1)*HID + n];
            uint32_t h, l; split2(v0, v1, h, l);
            *reinterpret_cast<uint32_t*>(g_wbt_hi + (size_t)mat*HID*RK + o2) = h;
            *reinterpret_cast<uint32_t*>(g_wbt_lo + (size_t)mat*HID*RK + o2) = l;
        }
    }
}

// ---------------------------------------------------------------------------
// Kernel 1: A-stage via HMMA, fp32 x split inline.  grid (128 Mtiles of 32, 3).
// ---------------------------------------------------------------------------
__global__ void __launch_bounds__(256) k_proja(
    const float* __restrict__ x,
    const float* __restrict__ b0, const float* __restrict__ b1, const float* __restrict__ b2)
{
    __shared__ __align__(16) __nv_bfloat16 XH[32*72], XL[32*72];
    __shared__ __align__(16) __nv_bfloat16 WH[64*72], WL[64*72];
    const int mat = blockIdx.y, m0 = blockIdx.x*32;
    const int tid = threadIdx.x, lid = tid & 31, wid = tid >> 5;
    const int mw = wid & 1, nw = wid >> 1;
    const uint32_t xh = s2u(XH), xl = s2u(XL), wh = s2u(WH), wl = s2u(WL);
    const __nv_bfloat16* wat_h = g_wat_hi + (size_t)mat*RK*HID;
    const __nv_bfloat16* wat_l = g_wat_lo + (size_t)mat*RK*HID;

    float acc[2][4];
#pragma unroll
    for (int nt = 0; nt < 2; nt++)
#pragma unroll
        for (int q = 0; q < 4; q++) acc[nt][q] = 0.0f;

    for (int kc = 0; kc < 16; kc++){
        __syncthreads();
        {
            int r = tid >> 3, c8 = (tid & 7)*8;
            float4 a = *reinterpret_cast<const float4*>(x + (size_t)(m0+r)*HID + kc*64 + c8);
            float4 b = *reinterpret_cast<const float4*>(x + (size_t)(m0+r)*HID + kc*64 + c8 + 4);
            uint32_t h0,l0,h1,l1,h2,l2,h3,l3;
            split2(a.x, a.y, h0, l0); split2(a.z, a.w, h1, l1);
            split2(b.x, b.y, h2, l2); split2(b.z, b.w, h3, l3);
            *reinterpret_cast<uint4*>(XH + r*72 + c8) = make_uint4(h0,h1,h2,h3);
            *reinterpret_cast<uint4*>(XL + r*72 + c8) = make_uint4(l0,l1,l2,l3);
#pragma unroll
            for (int it = 0; it < 2; it++){
                int e = tid + it*256;
                int wr = e >> 3, wc8 = (e & 7)*8;
                *reinterpret_cast<uint4*>(WH + wr*72 + wc8) =
                    *reinterpret_cast<const uint4*>(wat_h + (size_t)wr*HID + kc*64 + wc8);
                *reinterpret_cast<uint4*>(WL + wr*72 + wc8) =
                    *reinterpret_cast<const uint4*>(wat_l + (size_t)wr*HID + kc*64 + wc8);
            }
        }
        __syncthreads();
#pragma unroll
        for (int ks = 0; ks < 4; ks++){
            const int d0 = ks*16;
            int arow = mw*16 + (lid & 15);
            int acol = d0 + ((lid >> 4) << 3);
            uint32_t aH[4], aL[4];
            ldmx4(aH[0], aH[1], aH[2], aH[3], xh + (uint32_t)(arow*72 + acol)*2u);
            ldmx4(aL[0], aL[1], aL[2], aL[3], xl + (uint32_t)(arow*72 + acol)*2u);
            int brow = nw*16 + (lid & 7) + ((lid >> 4) << 3);
            int bcol = d0 + (((lid >> 3) & 1) << 3);
            uint32_t bh0, bh1, bh2, bh3, bl0, bl1, bl2, bl3;
            ldmx4(bh0, bh1, bh2, bh3, wh + (uint32_t)(brow*72 + bcol)*2u);
            ldmx4(bl0, bl1, bl2, bl3, wl + (uint32_t)(brow*72 + bcol)*2u);
            mma16816(acc[0], aH, bh0, bh1); mma16816(acc[1], aH, bh2, bh3);
            mma16816(acc[0], aH, bl0, bl1); mma16816(acc[1], aH, bl2, bl3);
            mma16816(acc[0], aL, bh0, bh1); mma16816(acc[1], aL, bh2, bh3);
        }
    }

    const float* ba = (mat==0) ? b0 : (mat==1 ? b1 : b2);
    __nv_bfloat16* th = g_thi + (size_t)mat*NT*RK;
    __nv_bfloat16* tl = g_tlo + (size_t)mat*NT*RK;
    int rlo = mw*16 + (lid >> 2);
#pragma unroll
    for (int nt = 0; nt < 2; nt++){
        int c0 = nw*16 + nt*8 + 2*(lid & 3);
        float ba0 = ba[c0], ba1 = ba[c0+1];
        uint32_t hw, lw;
        split2(acc[nt][0] + ba0, acc[nt][1] + ba1, hw, lw);
        *reinterpret_cast<uint32_t*>(th + (size_t)(m0+rlo)*RK + c0) = hw;
        *reinterpret_cast<uint32_t*>(tl + (size_t)(m0+rlo)*RK + c0) = lw;
        split2(acc[nt][2] + ba0, acc[nt][3] + ba1, hw, lw);
        *reinterpret_cast<uint32_t*>(th + (size_t)(m0+rlo+8)*RK + c0) = hw;
        *reinterpret_cast<uint32_t*>(tl + (size_t)(m0+rlo+8)*RK + c0) = lw;
    }
}

// ---------------------------------------------------------------------------
// Kernel 2: B-stage via HMMA, head-fused (unchanged).
// ---------------------------------------------------------------------------
__global__ void __launch_bounds__(256) k_projb(
    const float* __restrict__ b0, const float* __restrict__ b1, const float* __restrict__ b2)
{
    __shared__ __align__(16) __nv_bfloat16 TH[32*72], TL[32*72];
    __shared__ __align__(16) __nv_bfloat16 WH[2][64*72], WL[2][64*72];
    __shared__ float sqp[2][32*4];
    const int mat = blockIdx.y, m0 = blockIdx.x*32;
    const int tid = threadIdx.x, lid = tid & 31, wid = tid >> 5;
    const int mw = wid & 1, nw = wid >> 1;
    const uint32_t thp = s2u(TH), tlp = s2u(TL);
    const uint32_t whp[2] = { s2u(WH[0]), s2u(WH[1]) };
    const uint32_t wlp[2] = { s2u(WL[0]), s2u(WL[1]) };
    const __nv_bfloat16* wbt_h = g_wbt_hi + (size_t)mat*HID*RK;
    const __nv_bfloat16* wbt_l = g_wbt_lo + (size_t)mat*HID*RK;

    {
        int r = tid >> 3, c8 = (tid & 7)*8;
        cpa16(thp + (uint32_t)(r*72 + c8)*2u,
              g_thi + (size_t)mat*NT*RK + (size_t)(m0+r)*RK + c8);
        cpa16(tlp + (uint32_t)(r*72 + c8)*2u,
              g_tlo + (size_t)mat*NT*RK + (size_t)(m0+r)*RK + c8);
    }
    CP_COMMIT();
#pragma unroll
    for (int buf = 0; buf < 2; buf++){
#pragma unroll
        for (int it = 0; it < 2; it++){
            int e = tid + it*256;
            int wr = e >> 3, wc8 = (e & 7)*8;
            cpa16(whp[buf] + (uint32_t)(wr*72 + wc8)*2u,
                  wbt_h + (size_t)(buf*64 + wr)*RK + wc8);
            cpa16(wlp[buf] + (uint32_t)(wr*72 + wc8)*2u,
                  wbt_l + (size_t)(buf*64 + wr)*RK + wc8);
        }
        CP_COMMIT();
    }

    CP_WAIT(2);
    __syncthreads();

    uint32_t aH[4][4], aL[4][4];
#pragma unroll
    for (int ks = 0; ks < 4; ks++){
        int arow = mw*16 + (lid & 15);
        int acol = ks*16 + ((lid >> 4) << 3);
        ldmx4(aH[ks][0], aH[ks][1], aH[ks][2], aH[ks][3], thp + (uint32_t)(arow*72 + acol)*2u);
        ldmx4(aL[ks][0], aL[ks][1], aL[ks][2], aL[ks][3], tlp + (uint32_t)(arow*72 + acol)*2u);
    }

    const float* bb = (mat==0) ? b0 : (mat==1 ? b1 : b2);
    __nv_bfloat16* ph = (mat==0) ? g_qhi : (mat==1 ? g_khi : g_vhi);
    __nv_bfloat16* pl = (mat==0) ? g_qlo : (mat==1 ? g_klo : g_vlo);
    const int rl = mw*16 + (lid >> 2);

    for (int h = 0; h < 16; h++){
        CP_WAIT(1);
        __syncthreads();
        const int buf = h & 1;

        float acc[2][4];
#pragma unroll
        for (int nt = 0; nt < 2; nt++)
#pragma unroll
            for (int q = 0; q < 4; q++) acc[nt][q] = 0.0f;

#pragma unroll
        for (int ks = 0; ks < 4; ks++){
            int brow = nw*16 + (lid & 7) + ((lid >> 4) << 3);
            int bcol = ks*16 + (((lid >> 3) & 1) << 3);
            uint32_t bh0, bh1, bh2, bh3, bl0, bl1, bl2, bl3;
            ldmx4(bh0, bh1, bh2, bh3, whp[buf] + (uint32_t)(brow*72 + bcol)*2u);
            ldmx4(bl0, bl1, bl2, bl3, wlp[buf] + (uint32_t)(brow*72 + bcol)*2u);
            mma16816(acc[0], aH[ks], bh0, bh1); mma16816(acc[1], aH[ks], bh2, bh3);
            mma16816(acc[0], aH[ks], bl0, bl1); mma16816(acc[1], aH[ks], bl2, bl3);
            mma16816(acc[0], aL[ks], bh0, bh1); mma16816(acc[1], aL[ks], bh2, bh3);
        }

        float sqa0 = 0.f, sqa1 = 0.f;
#pragma unroll
        for (int nt = 0; nt < 2; nt++){
            int c0 = nw*16 + nt*8 + 2*(lid & 3);
            float bb0 = bb[h*64 + c0], bb1 = bb[h*64 + c0 + 1];
            float v00 = acc[nt][0] + bb0, v01 = acc[nt][1] + bb1;
            float v10 = acc[nt][2] + bb0, v11 = acc[nt][3] + bb1;
            int m1 = m0 + rl;
            int s1 = m1 >> 1, bh1i = (m1 & 1)*NH + h;
            uint32_t hw, lw;
            split2(v00, v01, hw, lw);
            *reinterpret_cast<uint32_t*>(ph + ((size_t)bh1i*SQ + s1)*DH + c0) = hw;
            *reinterpret_cast<uint32_t*>(pl + ((size_t)bh1i*SQ + s1)*DH + c0) = lw;
            int m2 = m1 + 8;
            int s2 = m2 >> 1, bh2i = (m2 & 1)*NH + h;
            split2(v10, v11, hw, lw);
            *reinterpret_cast<uint32_t*>(ph + ((size_t)bh2i*SQ + s2)*DH + c0) = hw;
            *reinterpret_cast<uint32_t*>(pl + ((size_t)bh2i*SQ + s2)*DH + c0) = lw;
            sqa0 += v00*v00 + v01*v01;
            sqa1 += v10*v10 + v11*v11;
        }
        sqa0 += __shfl_xor_sync(0xffffffffu, sqa0, 1);
        sqa0 += __shfl_xor_sync(0xffffffffu, sqa0, 2);
        sqa1 += __shfl_xor_sync(0xffffffffu, sqa1, 1);
        sqa1 += __shfl_xor_sync(0xffffffffu, sqa1, 2);
        if ((lid & 3) == 0){
            sqp[buf][rl*4 + nw]     = sqa0;
            sqp[buf][(rl+8)*4 + nw] = sqa1;
        }
        __syncthreads();
        if (mat < 2 && tid < 32){
            float s4 = sqp[buf][tid*4] + sqp[buf][tid*4+1] + sqp[buf][tid*4+2] + sqp[buf][tid*4+3];
            int m = m0 + tid;
            int s = m >> 1, bhh = (m & 1)*NH + h;
            g_sq[mat][(size_t)bhh*SQ + s] = s4;
        }
        if (h + 2 < 16){
#pragma unroll
            for (int it = 0; it < 2; it++){
                int e = tid + it*256;
                int wr = e >> 3, wc8 = (e & 7)*8;
                cpa16(whp[buf] + (uint32_t)(wr*72 + wc8)*2u,
                      wbt_h + (size_t)((h+2)*64 + wr)*RK + wc8);
                cpa16(wlp[buf] + (uint32_t)(wr*72 + wc8)*2u,
                      wbt_l + (size_t)((h+2)*64 + wr)*RK + wc8);
            }
        }
        CP_COMMIT();
    }
}

// ---------------------------------------------------------------------------
// Kernel 3: attention, 64-row Q tile, 3 CTAs/SM, shuffle-transposed epilogue.
// ---------------------------------------------------------------------------
#define QK_ST 72
#define SM_QSQ 0
#define SM_KSQ 256
#define SM_QHI 512
#define SM_QLO (SM_QHI + 9216)
#define SM_KHI (SM_QLO + 9216)
#define SM_KLO (SM_KHI + 9216)
#define SM_VHI (SM_KLO + 9216)
#define SM_VLO (SM_VHI + 9216)
#define SM_PHI (SM_VLO + 9216)
#define SM_PLO (SM_PHI + 9216)
#define SM_TOTAL (SM_PLO + 9216)   // 74240 bytes

__global__ void __launch_bounds__(256, 3) k_attn(float* __restrict__ out)
{
    extern __shared__ __align__(16) char sm[];
    const uint32_t sb = s2u(sm);
    const int tid = threadIdx.x, lid = tid & 31, wid = tid >> 5;
    const int bh = blockIdx.y, b = bh >> 4, h = bh & 15;
    const int q0r = blockIdx.x * 64;

    const size_t kvbase = (size_t)bh*SQ*DH;
    const int lr  = tid >> 3;
    const int lc8 = (tid & 7) * 8;
    const uint32_t lso = (uint32_t)(lr*QK_ST + lc8)*2u;

    // prologue: issue K(0)+ksq(0)
    {
#pragma unroll
        for (int it = 0; it < 2; it++){
            uint32_t so = lso + (uint32_t)(it*32*QK_ST)*2u;
            size_t go = kvbase + (size_t)(lr + it*32)*DH + lc8;
            cpa16(sb + SM_KHI + so, g_khi + go);
            cpa16(sb + SM_KLO + so, g_klo + go);
        }
        if (tid < 16)
            cpa16(sb + SM_KSQ + (uint32_t)tid*16u, g_sq[1] + (size_t)bh*SQ + tid*4);
        CP_COMMIT();
    }

    // resident Q tile (hi/lo) + qsq
    {
        const __nv_bfloat16* qh = g_qhi + ((size_t)bh*SQ + q0r)*DH;
        const __nv_bfloat16* ql = g_qlo + ((size_t)bh*SQ + q0r)*DH;
#pragma unroll
        for (int it = 0; it < 2; it++){
            uint32_t so = lso + (uint32_t)(it*32*QK_ST)*2u;
            size_t go = (size_t)(lr + it*32)*DH + lc8;
            *reinterpret_cast<uint4*>(sm + SM_QHI + so) =
                *reinterpret_cast<const uint4*>(qh + go);
            *reinterpret_cast<uint4*>(sm + SM_QLO + so) =
                *reinterpret_cast<const uint4*>(ql + go);
        }
        if (tid < 64)
            reinterpret_cast<float*>(sm + SM_QSQ)[tid] = g_sq[0][(size_t)bh*SQ + q0r + tid];
    }

    const int m0 = (wid & 1) * 32;
    const int n1 = (wid >> 1) * 16;
    const int lane_a = lid & 3;

    float acc2[2][2][4];
#pragma unroll
    for (int mt = 0; mt < 2; mt++)
#pragma unroll
        for (int nt = 0; nt < 2; nt++)
#pragma unroll
            for (int q = 0; q < 4; q++) acc2[mt][nt][q] = 0.0f;

    for (int kt = 0; kt < 32; kt++){
        __syncthreads();
        {
            const size_t off = kvbase + (size_t)kt*64*DH;
#pragma unroll
            for (int it = 0; it < 2; it++){
                uint32_t so = lso + (uint32_t)(it*32*QK_ST)*2u;
                size_t go = off + (size_t)(lr + it*32)*DH + lc8;
                cpa16(sb + SM_VHI + so, g_vhi + go);
                cpa16(sb + SM_VLO + so, g_vlo + go);
            }
            CP_COMMIT();
        }
        CP_WAIT(1);
        __syncthreads();

        // ---- GEMM1: qk = Q.K^T (3 bf16 passes) ----
        float acc1[2][2][4];
#pragma unroll
        for (int mt = 0; mt < 2; mt++)
#pragma unroll
            for (int nt = 0; nt < 2; nt++)
#pragma unroll
                for (int q = 0; q < 4; q++) acc1[mt][nt][q] = 0.0f;

#pragma unroll
        for (int ks = 0; ks < 4; ks++){
            const int d0 = ks*16;
            uint32_t aH[2][4], aL[2][4];
#pragma unroll
            for (int mt = 0; mt < 2; mt++){
                int row = m0 + mt*16 + (lid & 15);
                int col = d0 + ((lid >> 4) << 3);
                uint32_t ao = (uint32_t)(row*QK_ST + col)*2u;
                ldmx4(aH[mt][0], aH[mt][1], aH[mt][2], aH[mt][3], sb + SM_QHI + ao);
                ldmx4(aL[mt][0], aL[mt][1], aL[mt][2], aL[mt][3], sb + SM_QLO + ao);
            }
            int brow = n1 + (lid & 7) + ((lid >> 4) << 3);
            int bcol = d0 + (((lid >> 3) & 1) << 3);
            uint32_t bo = (uint32_t)(brow*QK_ST + bcol)*2u;
            uint32_t h0, h1, h2, h3, l0, l1, l2, l3;
            ldmx4(h0, h1, h2, h3, sb + SM_KHI + bo);
            ldmx4(l0, l1, l2, l3, sb + SM_KLO + bo);
#pragma unroll
            for (int mt = 0; mt < 2; mt++){
                mma16816(acc1[mt][0], aH[mt], h0, h1);
                mma16816(acc1[mt][1], aH[mt], h2, h3);
                mma16816(acc1[mt][0], aH[mt], l0, l1);
                mma16816(acc1[mt][1], aH[mt], l2, l3);
                mma16816(acc1[mt][0], aL[mt], h0, h1);
                mma16816(acc1[mt][1], aL[mt], h2, h3);
            }
        }

        // ---- epilogue: shuffle-transpose -> coalesced st.v4 scores, P split ----
        {
            const float* qsq = reinterpret_cast<const float*>(sm + SM_QSQ);
            const float* ksq = reinterpret_cast<const float*>(sm + SM_KSQ);
            const int col = n1 + 4*lane_a;
            const float4 kv = *reinterpret_cast<const float4*>(ksq + col);
#pragma unroll
            for (int mt = 0; mt < 2; mt++){
                int rlo = m0 + mt*16 + (lid >> 2);
#pragma unroll
                for (int half = 0; half < 2; half++){
                    int row = rlo + half*8;
                    // own col-pairs: Plo = cols {2a,2a+1}, Phi = cols {8+2a,8+2a+1}
                    u64 Plo = pk2f(acc1[mt][0][2*half], acc1[mt][0][2*half+1]);
                    u64 Phi = pk2f(acc1[mt][1][2*half], acc1[mt][1][2*half+1]);
                    // round A: xor2 — group pairs by 8-col half
                    u64 sendA = (lane_a < 2) ? Phi : Plo;
                    u64 recvA = __shfl_xor_sync(0xffffffffu, sendA, 2);
                    u64 A = (lane_a < 2) ? Plo : recvA;
                    u64 B = (lane_a < 2) ? recvA : Phi;
                    // round B: xor1 — assemble 4 consecutive cols
                    u64 sendB = (lane_a & 1) ? A : B;
                    u64 recvB = __shfl_xor_sync(0xffffffffu, sendB, 1);
                    u64 F = (lane_a & 1) ? recvB : A;
                    u64 S = (lane_a & 1) ? B : recvB;
                    float f0, f1, f2, f3;
                    up2f(F, f0, f1); up2f(S, f2, f3);
                    float qb = -0.0625f * qsq[row];
                    float sc0 = fmaf(0.125f, f0, qb - 0.0625f*kv.x);
                    float sc1 = fmaf(0.125f, f1, qb - 0.0625f*kv.y);
                    float sc2 = fmaf(0.125f, f2, qb - 0.0625f*kv.z);
                    float sc3 = fmaf(0.125f, f3, qb - 0.0625f*kv.w);
                    stg_cs4(out + CTXE + ((size_t)bh*SQ + (size_t)(q0r + row))*SQ + kt*64 + col,
                            sc0, sc1, sc2, sc3);
                    uint32_t hw0, lw0, hw1, lw1;
                    split2(__expf(sc0), __expf(sc1), hw0, lw0);
                    split2(__expf(sc2), __expf(sc3), hw1, lw1);
                    uint32_t po = (uint32_t)(row*QK_ST + col)*2u;
                    *reinterpret_cast<uint2*>(sm + SM_PHI + po) = make_uint2(hw0, hw1);
                    *reinterpret_cast<uint2*>(sm + SM_PLO + po) = make_uint2(lw0, lw1);
                }
            }
        }
        CP_WAIT(0);
        __syncthreads();

        // ---- prefetch K(kt+1)+ksq behind GEMM2 ----
        if (kt + 1 < 32){
            const size_t off = kvbase + (size_t)(kt+1)*64*DH;
#pragma unroll
            for (int it = 0; it < 2; it++){
                uint32_t so = lso + (uint32_t)(it*32*QK_ST)*2u;
                size_t go = off + (size_t)(lr + it*32)*DH + lc8;
                cpa16(sb + SM_KHI + so, g_khi + go);
                cpa16(sb + SM_KLO + so, g_klo + go);
            }
            if (tid < 16)
                cpa16(sb + SM_KSQ + (uint32_t)tid*16u,
                      g_sq[1] + (size_t)bh*SQ + (kt+1)*64 + tid*4);
            CP_COMMIT();
        } else {
            CP_COMMIT();
        }

        // ---- GEMM2: ctx += P.V (3 bf16 passes; V via ldmatrix.trans) ----
#pragma unroll
        for (int ks = 0; ks < 4; ks++){
            const int t0 = ks*16;
            uint32_t aH[2][4], aL[2][4];
#pragma unroll
            for (int mt = 0; mt < 2; mt++){
                int row = m0 + mt*16 + (lid & 15);
                int col = t0 + ((lid >> 4) << 3);
                uint32_t ao = (uint32_t)(row*QK_ST + col)*2u;
                ldmx4(aH[mt][0], aH[mt][1], aH[mt][2], aH[mt][3], sb + SM_PHI + ao);
                ldmx4(aL[mt][0], aL[mt][1], aL[mt][2], aL[mt][3], sb + SM_PLO + ao);
            }
            int brow = t0 + (lid & 7) + (((lid >> 3) & 1) << 3);
            int bcol = n1 + ((lid >> 4) << 3);
            uint32_t bo = (uint32_t)(brow*QK_ST + bcol)*2u;
            uint32_t h0, h1, h2, h3, l0, l1, l2, l3;
            ldmx4t(h0, h1, h2, h3, sb + SM_VHI + bo);
            ldmx4t(l0, l1, l2, l3, sb + SM_VLO + bo);
#pragma unroll
            for (int mt = 0; mt < 2; mt++){
                mma16816(acc2[mt][0], aH[mt], h0, h1);
                mma16816(acc2[mt][1], aH[mt], h2, h3);
                mma16816(acc2[mt][0], aH[mt], l0, l1);
                mma16816(acc2[mt][1], aH[mt], l2, l3);
                mma16816(acc2[mt][0], aL[mt], h0, h1);
                mma16816(acc2[mt][1], aL[mt], h2, h3);
            }
        }
    }

    // context epilogue: [s, b, h*64+d]
#pragma unroll
    for (int mt = 0; mt < 2; mt++){
        int rlo = m0 + mt*16 + (lid >> 2);
        float* o0 = out + (size_t)(q0r + rlo)*(BB*HID) + (size_t)b*HID + h*DH;
        float* o1 = o0 + (size_t)8*(BB*HID);
#pragma unroll
        for (int nt = 0; nt < 2; nt++){
            int col = n1 + nt*8 + 2*(lid & 3);
            *reinterpret_cast<float2*>(o0 + col) = make_float2(acc2[mt][nt][0], acc2[mt][nt][1]);
            *reinterpret_cast<float2*>(o1 + col) = make_float2(acc2[mt][nt][2], acc2[mt][nt][3]);
        }
    }
}

// ---------------------------------------------------------------------------
extern "C" void kernel_launch(void* const* d_in, const int* in_sizes, int n_in,
                              void* d_out, int out_size)
{
    const float* x   = (const float*)d_in[0];
    const float* wqa = (const float*)d_in[1];
    const float* bqa = (const float*)d_in[2];
    const float* wqb = (const float*)d_in[3];
    const float* bqb = (const float*)d_in[4];
    const float* wka = (const float*)d_in[5];
    const float* bka = (const float*)d_in[6];
    const float* wkb = (const float*)d_in[7];
    const float* bkb = (const float*)d_in[8];
    const float* wva = (const float*)d_in[9];
    const float* bva = (const float*)d_in[10];
    const float* wvb = (const float*)d_in[11];
    const float* bvb = (const float*)d_in[12];
    float* out = (float*)d_out;

    cudaFuncSetAttribute(k_attn, cudaFuncAttributeMaxDynamicSharedMemorySize, SM_TOTAL);

    k_splitw<<<dim3(16, 2, 3), 256>>>(wqa, wka, wva, wqb, wkb, wvb);
    k_proja<<<dim3(128, 3), 256>>>(x, bqa, bka, bva);
    k_projb<<<dim3(128, 3), 256>>>(bqb, bkb, bvb);
    k_attn<<<dim3(32, 32), 256, SM_TOTAL>>>(out);
}

// round 16
// speedup vs baseline: 1.1703x; 1.1703x over previous
#include <cuda_runtime.h>
#include <cuda_bf16.h>
#include <cstdint>

#define SQ   2048
#define BB   2
#define HID  1024
#define NH   16
#define DH   64
#define RK   64
#define NT   (SQ*BB)
#define BHN  (BB*NH)
#define CTXE ((size_t)SQ*BB*HID)

typedef unsigned long long u64;

// ---------------- device scratch (no allocation allowed) ----------------
__device__ float g_sq[2][BHN*SQ];          // ||q||^2, ||k||^2
__device__ __nv_bfloat16 g_wat_hi[3*RK*HID], g_wat_lo[3*RK*HID]; // wa^T [n][k]
__device__ __nv_bfloat16 g_wbt_hi[3*HID*RK], g_wbt_lo[3*HID*RK]; // wb^T [n][k]
__device__ __nv_bfloat16 g_thi[3*NT*RK], g_tlo[3*NT*RK];         // A-stage out
__device__ __nv_bfloat16 g_qhi[BHN*SQ*DH], g_qlo[BHN*SQ*DH];
__device__ __nv_bfloat16 g_khi[BHN*SQ*DH], g_klo[BHN*SQ*DH];
__device__ __nv_bfloat16 g_vhi[BHN*SQ*DH], g_vlo[BHN*SQ*DH];

__device__ __forceinline__ uint32_t s2u(const void* p){
    uint32_t a;
    asm("{ .reg .u64 t; cvta.to.shared.u64 t, %1; cvt.u32.u64 %0, t; }" : "=r"(a) : "l"(p));
    return a;
}

// ---------------- mma.sync helpers (baseline ISA) ------
__device__ __forceinline__ void ldmx4(uint32_t& r0, uint32_t& r1, uint32_t& r2, uint32_t& r3,
                                      uint32_t addr){
    asm volatile("ldmatrix.sync.aligned.m8n8.x4.shared.b16 {%0,%1,%2,%3}, [%4];"
        : "=r"(r0), "=r"(r1), "=r"(r2), "=r"(r3) : "r"(addr));
}
__device__ __forceinline__ void ldmx4t(uint32_t& r0, uint32_t& r1, uint32_t& r2, uint32_t& r3,
                                       uint32_t addr){
    asm volatile("ldmatrix.sync.aligned.m8n8.x4.trans.shared.b16 {%0,%1,%2,%3}, [%4];"
        : "=r"(r0), "=r"(r1), "=r"(r2), "=r"(r3) : "r"(addr));
}
__device__ __forceinline__ void mma16816(float* d, const uint32_t* a, uint32_t b0, uint32_t b1){
    asm("mma.sync.aligned.m16n8k16.row.col.f32.bf16.bf16.f32 "
        "{%0,%1,%2,%3},{%4,%5,%6,%7},{%8,%9},{%0,%1,%2,%3};"
        : "+f"(d[0]), "+f"(d[1]), "+f"(d[2]), "+f"(d[3])
        : "r"(a[0]), "r"(a[1]), "r"(a[2]), "r"(a[3]), "r"(b0), "r"(b1));
}
// Packed bf16 hi/lo split.
__device__ __forceinline__ void split2(float x, float y, uint32_t& hi, uint32_t& lo){
    uint32_t h;
    asm("cvt.rn.bf16x2.f32 %0, %1, %2;" : "=r"(h) : "f"(y), "f"(x));
    float xh = __uint_as_float(h << 16);
    float yh = __uint_as_float(h & 0xFFFF0000u);
    float xl = x - xh, yl = y - yh;
    uint32_t l;
    asm("cvt.rn.bf16x2.f32 %0, %1, %2;" : "=r"(l) : "f"(yl), "f"(xl));
    hi = h; lo = l;
}
__device__ __forceinline__ void cpa16(uint32_t dst, const void* src){
    asm volatile("cp.async.cg.shared.global [%0], [%1], 16;" :: "r"(dst), "l"(src));
}
#define CP_COMMIT() asm volatile("cp.async.commit_group;")
#define CP_WAIT(n)  asm volatile("cp.async.wait_group %0;" :: "n"(n))
__device__ __forceinline__ void stg_cs2(float* p, float a, float b){
    asm volatile("st.global.cs.v2.f32 [%0], {%1,%2};" :: "l"(p), "f"(a), "f"(b) : "memory");
}

// ---------------------------------------------------------------------------
// Kernel 0: transpose+split weights.
// ---------------------------------------------------------------------------
__global__ void __launch_bounds__(256) k_splitw(
    const float* __restrict__ wqa, const float* __restrict__ wka, const float* __restrict__ wva,
    const float* __restrict__ wqb, const float* __restrict__ wkb, const float* __restrict__ wvb)
{
    const int mat = blockIdx.z;
    if (blockIdx.y == 0){
        const float* wa = (mat==0) ? wqa : (mat==1 ? wka : wva);
#pragma unroll
        for (int it = 0; it < 8; it++){
            int o2 = (blockIdx.x*2048 + it*256 + threadIdx.x)*2;
            int n = o2 >> 10, k = o2 & 1023;
            float v0 = wa[(size_t)k*RK + n];
            float v1 = wa[(size_t)(k+1)*RK + n];
            uint32_t h, l; split2(v0, v1, h, l);
            *reinterpret_cast<uint32_t*>(g_wat_hi + (size_t)mat*RK*HID + o2) = h;
            *reinterpret_cast<uint32_t*>(g_wat_lo + (size_t)mat*RK*HID + o2) = l;
        }
    } else {
        const float* wb = (mat==0) ? wqb : (mat==1 ? wkb : wvb);
#pragma unroll
        for (int it = 0; it < 8; it++){
            int o2 = (blockIdx.x*2048 + it*256 + threadIdx.x)*2;
            int n = o2 >> 6, k = o2 & 63;
            float v0 = wb[(size_t)k*HID + n];
            float v1 = wb[(size_t)(k+1)*HID + n];
            uint32_t h, l; split2(v0, v1, h, l);
            *reinterpret_cast<uint32_t*>(g_wbt_hi + (size_t)mat*HID*RK + o2) = h;
            *reinterpret_cast<uint32_t*>(g_wbt_lo + (size_t)mat*HID*RK + o2) = l;
        }
    }
}

// ---------------------------------------------------------------------------
// Kernel 1: A-stage via HMMA, fp32 x split inline.  grid (128 Mtiles of 32, 3).
// ---------------------------------------------------------------------------
__global__ void __launch_bounds__(256) k_proja(
    const float* __restrict__ x,
    const float* __restrict__ b0, const float* __restrict__ b1, const float* __restrict__ b2)
{
    __shared__ __align__(16) __nv_bfloat16 XH[32*72], XL[32*72];
    __shared__ __align__(16) __nv_bfloat16 WH[64*72], WL[64*72];
    const int mat = blockIdx.y, m0 = blockIdx.x*32;
    const int tid = threadIdx.x, lid = tid & 31, wid = tid >> 5;
    const int mw = wid & 1, nw = wid >> 1;
    const uint32_t xh = s2u(XH), xl = s2u(XL), wh = s2u(WH), wl = s2u(WL);
    const __nv_bfloat16* wat_h = g_wat_hi + (size_t)mat*RK*HID;
    const __nv_bfloat16* wat_l = g_wat_lo + (size_t)mat*RK*HID;

    float acc[2][4];
#pragma unroll
    for (int nt = 0; nt < 2; nt++)
#pragma unroll
        for (int q = 0; q < 4; q++) acc[nt][q] = 0.0f;

    for (int kc = 0; kc < 16; kc++){
        __syncthreads();
        {
            int r = tid >> 3, c8 = (tid & 7)*8;
            float4 a = *reinterpret_cast<const float4*>(x + (size_t)(m0+r)*HID + kc*64 + c8);
            float4 b = *reinterpret_cast<const float4*>(x + (size_t)(m0+r)*HID + kc*64 + c8 + 4);
            uint32_t h0,l0,h1,l1,h2,l2,h3,l3;
            split2(a.x, a.y, h0, l0); split2(a.z, a.w, h1, l1);
            split2(b.x, b.y, h2, l2); split2(b.z, b.w, h3, l3);
            *reinterpret_cast<uint4*>(XH + r*72 + c8) = make_uint4(h0,h1,h2,h3);
            *reinterpret_cast<uint4*>(XL + r*72 + c8) = make_uint4(l0,l1,l2,l3);
#pragma unroll
            for (int it = 0; it < 2; it++){
                int e = tid + it*256;
                int wr = e >> 3, wc8 = (e & 7)*8;
                *reinterpret_cast<uint4*>(WH + wr*72 + wc8) =
                    *reinterpret_cast<const uint4*>(wat_h + (size_t)wr*HID + kc*64 + wc8);
                *reinterpret_cast<uint4*>(WL + wr*72 + wc8) =
                    *reinterpret_cast<const uint4*>(wat_l + (size_t)wr*HID + kc*64 + wc8);
            }
        }
        __syncthreads();
#pragma unroll
        for (int ks = 0; ks < 4; ks++){
            const int d0 = ks*16;
            int arow = mw*16 + (lid & 15);
            int acol = d0 + ((lid >> 4) << 3);
            uint32_t aH[4], aL[4];
            ldmx4(aH[0], aH[1], aH[2], aH[3], xh + (uint32_t)(arow*72 + acol)*2u);
            ldmx4(aL[0], aL[1], aL[2], aL[3], xl + (uint32_t)(arow*72 + acol)*2u);
            int brow = nw*16 + (lid & 7) + ((lid >> 4) << 3);
            int bcol = d0 + (((lid >> 3) & 1) << 3);
            uint32_t bh0, bh1, bh2, bh3, bl0, bl1, bl2, bl3;
            ldmx4(bh0, bh1, bh2, bh3, wh + (uint32_t)(brow*72 + bcol)*2u);
            ldmx4(bl0, bl1, bl2, bl3, wl + (uint32_t)(brow*72 + bcol)*2u);
            mma16816(acc[0], aH, bh0, bh1); mma16816(acc[1], aH, bh2, bh3);
            mma16816(acc[0], aH, bl0, bl1); mma16816(acc[1], aH, bl2, bl3);
            mma16816(acc[0], aL, bh0, bh1); mma16816(acc[1], aL, bh2, bh3);
        }
    }

    const float* ba = (mat==0) ? b0 : (mat==1 ? b1 : b2);
    __nv_bfloat16* th = g_thi + (size_t)mat*NT*RK;
    __nv_bfloat16* tl = g_tlo + (size_t)mat*NT*RK;
    int rlo = mw*16 + (lid >> 2);
#pragma unroll
    for (int nt = 0; nt < 2; nt++){
        int c0 = nw*16 + nt*8 + 2*(lid & 3);
        float ba0 = ba[c0], ba1 = ba[c0+1];
        uint32_t hw, lw;
        split2(acc[nt][0] + ba0, acc[nt][1] + ba1, hw, lw);
        *reinterpret_cast<uint32_t*>(th + (size_t)(m0+rlo)*RK + c0) = hw;
        *reinterpret_cast<uint32_t*>(tl + (size_t)(m0+rlo)*RK + c0) = lw;
        split2(acc[nt][2] + ba0, acc[nt][3] + ba1, hw, lw);
        *reinterpret_cast<uint32_t*>(th + (size_t)(m0+rlo+8)*RK + c0) = hw;
        *reinterpret_cast<uint32_t*>(tl + (size_t)(m0+rlo+8)*RK + c0) = lw;
    }
}

// ---------------------------------------------------------------------------
// Kernel 2: B-stage via HMMA, head-fused (unchanged).
// ---------------------------------------------------------------------------
__global__ void __launch_bounds__(256) k_projb(
    const float* __restrict__ b0, const float* __restrict__ b1, const float* __restrict__ b2)
{
    __shared__ __align__(16) __nv_bfloat16 TH[32*72], TL[32*72];
    __shared__ __align__(16) __nv_bfloat16 WH[2][64*72], WL[2][64*72];
    __shared__ float sqp[2][32*4];
    const int mat = blockIdx.y, m0 = blockIdx.x*32;
    const int tid = threadIdx.x, lid = tid & 31, wid = tid >> 5;
    const int mw = wid & 1, nw = wid >> 1;
    const uint32_t thp = s2u(TH), tlp = s2u(TL);
    const uint32_t whp[2] = { s2u(WH[0]), s2u(WH[1]) };
    const uint32_t wlp[2] = { s2u(WL[0]), s2u(WL[1]) };
    const __nv_bfloat16* wbt_h = g_wbt_hi + (size_t)mat*HID*RK;
    const __nv_bfloat16* wbt_l = g_wbt_lo + (size_t)mat*HID*RK;

    {
        int r = tid >> 3, c8 = (tid & 7)*8;
        cpa16(thp + (uint32_t)(r*72 + c8)*2u,
              g_thi + (size_t)mat*NT*RK + (size_t)(m0+r)*RK + c8);
        cpa16(tlp + (uint32_t)(r*72 + c8)*2u,
              g_tlo + (size_t)mat*NT*RK + (size_t)(m0+r)*RK + c8);
    }
    CP_COMMIT();
#pragma unroll
    for (int buf = 0; buf < 2; buf++){
#pragma unroll
        for (int it = 0; it < 2; it++){
            int e = tid + it*256;
            int wr = e >> 3, wc8 = (e & 7)*8;
            cpa16(whp[buf] + (uint32_t)(wr*72 + wc8)*2u,
                  wbt_h + (size_t)(buf*64 + wr)*RK + wc8);
            cpa16(wlp[buf] + (uint32_t)(wr*72 + wc8)*2u,
                  wbt_l + (size_t)(buf*64 + wr)*RK + wc8);
        }
        CP_COMMIT();
    }

    CP_WAIT(2);
    __syncthreads();

    uint32_t aH[4][4], aL[4][4];
#pragma unroll
    for (int ks = 0; ks < 4; ks++){
        int arow = mw*16 + (lid & 15);
        int acol = ks*16 + ((lid >> 4) << 3);
        ldmx4(aH[ks][0], aH[ks][1], aH[ks][2], aH[ks][3], thp + (uint32_t)(arow*72 + acol)*2u);
        ldmx4(aL[ks][0], aL[ks][1], aL[ks][2], aL[ks][3], tlp + (uint32_t)(arow*72 + acol)*2u);
    }

    const float* bb = (mat==0) ? b0 : (mat==1 ? b1 : b2);
    __nv_bfloat16* ph = (mat==0) ? g_qhi : (mat==1 ? g_khi : g_vhi);
    __nv_bfloat16* pl = (mat==0) ? g_qlo : (mat==1 ? g_klo : g_vlo);
    const int rl = mw*16 + (lid >> 2);

    for (int h = 0; h < 16; h++){
        CP_WAIT(1);
        __syncthreads();
        const int buf = h & 1;

        float acc[2][4];
#pragma unroll
        for (int nt = 0; nt < 2; nt++)
#pragma unroll
            for (int q = 0; q < 4; q++) acc[nt][q] = 0.0f;

#pragma unroll
        for (int ks = 0; ks < 4; ks++){
            int brow = nw*16 + (lid & 7) + ((lid >> 4) << 3);
            int bcol = ks*16 + (((lid >> 3) & 1) << 3);
            uint32_t bh0, bh1, bh2, bh3, bl0, bl1, bl2, bl3;
            ldmx4(bh0, bh1, bh2, bh3, whp[buf] + (uint32_t)(brow*72 + bcol)*2u);
            ldmx4(bl0, bl1, bl2, bl3, wlp[buf] + (uint32_t)(brow*72 + bcol)*2u);
            mma16816(acc[0], aH[ks], bh0, bh1); mma16816(acc[1], aH[ks], bh2, bh3);
            mma16816(acc[0], aH[ks], bl0, bl1); mma16816(acc[1], aH[ks], bl2, bl3);
            mma16816(acc[0], aL[ks], bh0, bh1); mma16816(acc[1], aL[ks], bh2, bh3);
        }

        float sqa0 = 0.f, sqa1 = 0.f;
#pragma unroll
        for (int nt = 0; nt < 2; nt++){
            int c0 = nw*16 + nt*8 + 2*(lid & 3);
            float bb0 = bb[h*64 + c0], bb1 = bb[h*64 + c0 + 1];
            float v00 = acc[nt][0] + bb0, v01 = acc[nt][1] + bb1;
            float v10 = acc[nt][2] + bb0, v11 = acc[nt][3] + bb1;
            int m1 = m0 + rl;
            int s1 = m1 >> 1, bh1i = (m1 & 1)*NH + h;
            uint32_t hw, lw;
            split2(v00, v01, hw, lw);
            *reinterpret_cast<uint32_t*>(ph + ((size_t)bh1i*SQ + s1)*DH + c0) = hw;
            *reinterpret_cast<uint32_t*>(pl + ((size_t)bh1i*SQ + s1)*DH + c0) = lw;
            int m2 = m1 + 8;
            int s2 = m2 >> 1, bh2i = (m2 & 1)*NH + h;
            split2(v10, v11, hw, lw);
            *reinterpret_cast<uint32_t*>(ph + ((size_t)bh2i*SQ + s2)*DH + c0) = hw;
            *reinterpret_cast<uint32_t*>(pl + ((size_t)bh2i*SQ + s2)*DH + c0) = lw;
            sqa0 += v00*v00 + v01*v01;
            sqa1 += v10*v10 + v11*v11;
        }
        sqa0 += __shfl_xor_sync(0xffffffffu, sqa0, 1);
        sqa0 += __shfl_xor_sync(0xffffffffu, sqa0, 2);
        sqa1 += __shfl_xor_sync(0xffffffffu, sqa1, 1);
        sqa1 += __shfl_xor_sync(0xffffffffu, sqa1, 2);
        if ((lid & 3) == 0){
            sqp[buf][rl*4 + nw]     = sqa0;
            sqp[buf][(rl+8)*4 + nw] = sqa1;
        }
        __syncthreads();
        if (mat < 2 && tid < 32){
            float s4 = sqp[buf][tid*4] + sqp[buf][tid*4+1] + sqp[buf][tid*4+2] + sqp[buf][tid*4+3];
            int m = m0 + tid;
            int s = m >> 1, bhh = (m & 1)*NH + h;
            g_sq[mat][(size_t)bhh*SQ + s] = s4;
        }
        if (h + 2 < 16){
#pragma unroll
            for (int it = 0; it < 2; it++){
                int e = tid + it*256;
                int wr = e >> 3, wc8 = (e & 7)*8;
                cpa16(whp[buf] + (uint32_t)(wr*72 + wc8)*2u,
                      wbt_h + (size_t)((h+2)*64 + wr)*RK + wc8);
                cpa16(wlp[buf] + (uint32_t)(wr*72 + wc8)*2u,
                      wbt_l + (size_t)((h+2)*64 + wr)*RK + wc8);
            }
        }
        CP_COMMIT();
    }
}

// ---------------------------------------------------------------------------
// Kernel 3: attention, FA2-style register P.  128 threads, 64-row Q tile,
// each warp owns 16 rows x FULL 64-key span.  55.8KB smem -> 4 CTAs/SM.
// ---------------------------------------------------------------------------
#define QK_ST 72
#define SM_QSQ 0
#define SM_KSQ 256
#define SM_QHI 512
#define SM_QLO (SM_QHI + 9216)
#define SM_KHI (SM_QLO + 9216)
#define SM_KLO (SM_KHI + 9216)
#define SM_VHI (SM_KLO + 9216)
#define SM_VLO (SM_VHI + 9216)
#define SM_TOTAL (SM_VLO + 9216)   // 55808 bytes

__global__ void __launch_bounds__(128, 4) k_attn(float* __restrict__ out)
{
    extern __shared__ __align__(16) char sm[];
    const uint32_t sb = s2u(sm);
    const int tid = threadIdx.x, lid = tid & 31, wid = tid >> 5;   // 4 warps
    const int bh = blockIdx.y, b = bh >> 4, h = bh & 15;
    const int q0r = blockIdx.x * 64;

    const size_t kvbase = (size_t)bh*SQ*DH;

    // prologue: issue K(0)+ksq(0)
    {
#pragma unroll
        for (int it = 0; it < 4; it++){
            int e = tid + it*128;
            int r = e >> 3, c8 = (e & 7)*8;
            uint32_t so = (uint32_t)(r*QK_ST + c8)*2u;
            size_t go = kvbase + (size_t)r*DH + c8;
            cpa16(sb + SM_KHI + so, g_khi + go);
            cpa16(sb + SM_KLO + so, g_klo + go);
        }
        if (tid < 16)
            cpa16(sb + SM_KSQ + (uint32_t)tid*16u, g_sq[1] + (size_t)bh*SQ + tid*4);
        CP_COMMIT();
    }

    // resident Q tile (hi/lo) + qsq
    {
        const __nv_bfloat16* qh = g_qhi + ((size_t)bh*SQ + q0r)*DH;
        const __nv_bfloat16* ql = g_qlo + ((size_t)bh*SQ + q0r)*DH;
#pragma unroll
        for (int it = 0; it < 4; it++){
            int e = tid + it*128;
            int r = e >> 3, c8 = (e & 7)*8;
            uint32_t so = (uint32_t)(r*QK_ST + c8)*2u;
            size_t go = (size_t)r*DH + c8;
            *reinterpret_cast<uint4*>(sm + SM_QHI + so) =
                *reinterpret_cast<const uint4*>(qh + go);
            *reinterpret_cast<uint4*>(sm + SM_QLO + so) =
                *reinterpret_cast<const uint4*>(ql + go);
        }
        if (tid < 64)
            reinterpret_cast<float*>(sm + SM_QSQ)[tid] = g_sq[0][(size_t)bh*SQ + q0r + tid];
    }

    const int m0 = wid * 16;     // warp M base (16 rows per warp)

    float acc2[8][4];            // ctx accum: full 64 dims per warp
#pragma unroll
    for (int nt = 0; nt < 8; nt++)
#pragma unroll
        for (int q = 0; q < 4; q++) acc2[nt][q] = 0.0f;

    for (int kt = 0; kt < 32; kt++){
        __syncthreads();             // GEMM2(kt-1) done -> V buffer free
        {
            const size_t off = kvbase + (size_t)kt*64*DH;
#pragma unroll
            for (int it = 0; it < 4; it++){
                int e = tid + it*128;
                int r = e >> 3, c8 = (e & 7)*8;
                uint32_t so = (uint32_t)(r*QK_ST + c8)*2u;
                size_t go = off + (size_t)r*DH + c8;
                cpa16(sb + SM_VHI + so, g_vhi + go);
                cpa16(sb + SM_VLO + so, g_vlo + go);
            }
            CP_COMMIT();
        }
        CP_WAIT(1);                  // K(kt)+ksq landed; V in flight
        __syncthreads();

        // ---- GEMM1: qk = Q.K^T, full N=64 per warp (3 bf16 passes) ----
        float acc1[8][4];
#pragma unroll
        for (int nt = 0; nt < 8; nt++)
#pragma unroll
            for (int q = 0; q < 4; q++) acc1[nt][q] = 0.0f;

#pragma unroll
        for (int ks = 0; ks < 4; ks++){
            const int d0 = ks*16;
            uint32_t aH[4], aL[4];
            {
                int row = m0 + (lid & 15);
                int col = d0 + ((lid >> 4) << 3);
                uint32_t ao = (uint32_t)(row*QK_ST + col)*2u;
                ldmx4(aH[0], aH[1], aH[2], aH[3], sb + SM_QHI + ao);
                ldmx4(aL[0], aL[1], aL[2], aL[3], sb + SM_QLO + ao);
            }
#pragma unroll
            for (int nb = 0; nb < 4; nb++){
                int brow = nb*16 + (lid & 7) + ((lid >> 4) << 3);
                int bcol = d0 + (((lid >> 3) & 1) << 3);
                uint32_t bo = (uint32_t)(brow*QK_ST + bcol)*2u;
                uint32_t h0, h1, h2, h3, l0, l1, l2, l3;
                ldmx4(h0, h1, h2, h3, sb + SM_KHI + bo);
                ldmx4(l0, l1, l2, l3, sb + SM_KLO + bo);
                mma16816(acc1[2*nb],   aH, h0, h1);
                mma16816(acc1[2*nb+1], aH, h2, h3);
                mma16816(acc1[2*nb],   aH, l0, l1);
                mma16816(acc1[2*nb+1], aH, l2, l3);
                mma16816(acc1[2*nb],   aL, h0, h1);
                mma16816(acc1[2*nb+1], aL, h2, h3);
            }
        }

        // ---- epilogue: scores -> gmem (.cs); P = exp -> REGISTER A-frags ----
        uint32_t PH[4][4], PL[4][4];
        {
            const float* qsq = reinterpret_cast<const float*>(sm + SM_QSQ);
            const float* ksq = reinterpret_cast<const float*>(sm + SM_KSQ);
            int r0 = m0 + (lid >> 2);
            float q0 = qsq[r0], q1 = qsq[r0 + 8];
            float* sr0 = out + CTXE + ((size_t)bh*SQ + (size_t)(q0r + r0))*SQ + kt*64;
            float* sr1 = sr0 + (size_t)8*SQ;
#pragma unroll
            for (int nt = 0; nt < 8; nt++){
                int col = nt*8 + 2*(lid & 3);
                float k0 = ksq[col], k1 = ksq[col+1];
                float s00 = fmaf(0.125f, acc1[nt][0], -0.0625f*(q0 + k0));
                float s01 = fmaf(0.125f, acc1[nt][1], -0.0625f*(q0 + k1));
                float s10 = fmaf(0.125f, acc1[nt][2], -0.0625f*(q1 + k0));
                float s11 = fmaf(0.125f, acc1[nt][3], -0.0625f*(q1 + k1));
                stg_cs2(sr0 + col, s00, s01);
                stg_cs2(sr1 + col, s10, s11);
                // C(m16n8) -> A(m16k16) fragment mapping:
                // frag[j][2*(nt&1)+0] = rows r,   k-cols = this nt's n-cols
                // frag[j][2*(nt&1)+1] = rows r+8
                int j = nt >> 1, hf = (nt & 1)*1;
                split2(__expf(s00), __expf(s01), PH[j][2*hf],   PL[j][2*hf]);
                split2(__expf(s10), __expf(s11), PH[j][2*hf+1], PL[j][2*hf+1]);
            }
        }
        CP_WAIT(0);            // V(kt) landed
        __syncthreads();       // all warps done reading K buffer

        // ---- prefetch K(kt+1)+ksq behind GEMM2 ----
        if (kt + 1 < 32){
            const size_t off = kvbase + (size_t)(kt+1)*64*DH;
#pragma unroll
            for (int it = 0; it < 4; it++){
                int e = tid + it*128;
                int r = e >> 3, c8 = (e & 7)*8;
                uint32_t so = (uint32_t)(r*QK_ST + c8)*2u;
                size_t go = off + (size_t)r*DH + c8;
                cpa16(sb + SM_KHI + so, g_khi + go);
                cpa16(sb + SM_KLO + so, g_klo + go);
            }
            if (tid < 16)
                cpa16(sb + SM_KSQ + (uint32_t)tid*16u,
                      g_sq[1] + (size_t)bh*SQ + (kt+1)*64 + tid*4);
            CP_COMMIT();
        } else {
            CP_COMMIT();
        }

        // ---- GEMM2: ctx += P.V — P straight from registers, V via ldmatrix.trans ----
#pragma unroll
        for (int j = 0; j < 4; j++){
            const int t0 = j*16;
#pragma unroll
            for (int nc = 0; nc < 4; nc++){
                int brow = t0 + (lid & 7) + (((lid >> 3) & 1) << 3);
                int bcol = nc*16 + ((lid >> 4) << 3);
                uint32_t bo = (uint32_t)(brow*QK_ST + bcol)*2u;
                uint32_t h0, h1, h2, h3, l0, l1, l2, l3;
                ldmx4t(h0, h1, h2, h3, sb + SM_VHI + bo);
                ldmx4t(l0, l1, l2, l3, sb + SM_VLO + bo);
                mma16816(acc2[2*nc],   PH[j], h0, h1);
                mma16816(acc2[2*nc+1], PH[j], h2, h3);
                mma16816(acc2[2*nc],   PH[j], l0, l1);
                mma16816(acc2[2*nc+1], PH[j], l2, l3);
                mma16816(acc2[2*nc],   PL[j], h0, h1);
                mma16816(acc2[2*nc+1], PL[j], h2, h3);
            }
        }
    }

    // context epilogue: [s, b, h*64+d]
    {
        int r0 = m0 + (lid >> 2);
        float* o0 = out + (size_t)(q0r + r0)*(BB*HID) + (size_t)b*HID + h*DH;
        float* o1 = o0 + (size_t)8*(BB*HID);
#pragma unroll
        for (int nt = 0; nt < 8; nt++){
            int col = nt*8 + 2*(lid & 3);
            *reinterpret_cast<float2*>(o0 + col) = make_float2(acc2[nt][0], acc2[nt][1]);
            *reinterpret_cast<float2*>(o1 + col) = make_float2(acc2[nt][2], acc2[nt][3]);
        }
    }
}

// ---------------------------------------------------------------------------
extern "C" void kernel_launch(void* const* d_in, const int* in_sizes, int n_in,
                              void* d_out, int out_size)
{
    const float* x   = (const float*)d_in[0];
    const float* wqa = (const float*)d_in[1];
    const float* bqa = (const float*)d_in[2];
    const float* wqb = (const float*)d_in[3];
    const float* bqb = (const float*)d_in[4];
    const float* wka = (const float*)d_in[5];
    const float* bka = (const float*)d_in[6];
    const float* wkb = (const float*)d_in[7];
    const float* bkb = (const float*)d_in[8];
    const float* wva = (const float*)d_in[9];
    const float* bva = (const float*)d_in[10];
    const float* wvb = (const float*)d_in[11];
    const float* bvb = (const float*)d_in[12];
    float* out = (float*)d_out;

    cudaFuncSetAttribute(k_attn, cudaFuncAttributeMaxDynamicSharedMemorySize, SM_TOTAL);

    k_splitw<<<dim3(16, 2, 3), 256>>>(wqa, wka, wva, wqb, wkb, wvb);
    k_proja<<<dim3(128, 3), 256>>>(x, bqa, bka, bva);
    k_projb<<<dim3(128, 3), 256>>>(bqb, bkb, bvb);
    k_attn<<<dim3(32, 32), 128, SM_TOTAL>>>(out);
}